// round 3
// baseline (speedup 1.0000x reference)
#include <cuda_runtime.h>
#include <cuda_fp16.h>
#include <cstdint>

#define NPTS   2048
#define NBATCH 8
#define NSAMP  64
#define R2     0.36f

// 4 MB fp16 feature table: f[b][m][c], c = 0..127
__device__ __half g_feat_h[NBATCH * NPTS * 128];

// packed fp32x2 FMA (sm_100+): d.lo += a.lo*b.lo ; d.hi += a.hi*b.hi
__device__ __forceinline__ void ffma2(unsigned long long& d,
                                      unsigned long long a,
                                      unsigned long long b) {
    asm("fma.rn.f32x2 %0, %1, %2, %0;" : "+l"(d) : "l"(a), "l"(b));
}
__device__ __forceinline__ unsigned long long pack2(float lo, float hi) {
    unsigned long long r;
    asm("mov.b64 %0, {%1, %2};" : "=l"(r) : "f"(lo), "f"(hi));
    return r;
}
__device__ __forceinline__ void unpack2(unsigned long long v, float& lo, float& hi) {
    asm("mov.b64 {%0, %1}, %2;" : "=f"(lo), "=f"(hi) : "l"(v));
}

// ---------------------------------------------------------------------------
// Kernel 1: f[b,m,:] = relu(W2*relu(W1*x+b1)+b2), fp16 output.
// Warp = 32 points (lanes) x one 32-channel quarter. Layer 2 uses FFMA2
// (packed fp32x2): acc[k] accumulates channel pair (cbase+2k, cbase+2k+1)
// in full fp32. W2 stored transposed in smem so one broadcast LDS.128
// yields two channel pairs for a given o.
// ---------------------------------------------------------------------------
__global__ __launch_bounds__(256) void feat_kernel(
    const float* __restrict__ x, const float* __restrict__ W1,
    const float* __restrict__ b1, const float* __restrict__ W2,
    const float* __restrict__ b2)
{
    __shared__ float sW1[64 * 3];
    __shared__ float sb1[64];
    __shared__ float sb2[128];
    __shared__ float sW2t[64 * 128];   // [o][c] = W2[c][o], 32 KB

    const int tid = threadIdx.x;
    for (int i = tid; i < 192; i += 256) sW1[i] = W1[i];
    for (int i = tid; i < 64;  i += 256) sb1[i] = b1[i];
    for (int i = tid; i < 128; i += 256) sb2[i] = b2[i];
    for (int i = tid; i < 64 * 128; i += 256) {
        const int o = i >> 7, c = i & 127;
        sW2t[o * 128 + c] = W2[c * 64 + o];
    }
    __syncthreads();

    const int lane    = tid & 31;
    const int gwarp   = blockIdx.x * 8 + (tid >> 5);  // 0..2047
    const int quarter = gwarp & 3;
    const int cbase   = quarter * 32;
    const int p       = (gwarp >> 2) * 32 + lane;     // 0..16383

    const float x0 = x[p * 3 + 0];
    const float x1 = x[p * 3 + 1];
    const float x2 = x[p * 3 + 2];

    float h1[64];
#pragma unroll
    for (int o = 0; o < 64; o++) {
        float v = sb1[o];
        v = fmaf(sW1[o * 3 + 0], x0, v);
        v = fmaf(sW1[o * 3 + 1], x1, v);
        v = fmaf(sW1[o * 3 + 2], x2, v);
        h1[o] = fmaxf(v, 0.0f);
    }

    unsigned long long acc[16];
    const unsigned long long* b2p =
        reinterpret_cast<const unsigned long long*>(sb2 + cbase);
#pragma unroll
    for (int k = 0; k < 16; k++) acc[k] = b2p[k];

#pragma unroll 4
    for (int o = 0; o < 64; o++) {
        const unsigned long long hh = pack2(h1[o], h1[o]);
        const ulonglong2* wrow =
            reinterpret_cast<const ulonglong2*>(sW2t + o * 128 + cbase);
#pragma unroll
        for (int j = 0; j < 8; j++) {
            const ulonglong2 w = wrow[j];   // LDS.128, warp-broadcast
            ffma2(acc[2 * j + 0], w.x, hh);
            ffma2(acc[2 * j + 1], w.y, hh);
        }
    }

    // relu -> fp16; word k = half2(channel cbase+2k, cbase+2k+1)
    uint32_t hw[8];
#pragma unroll
    for (int k = 0; k < 8; k++) {
        float l0, h0, l1, h1v;
        unpack2(acc[2 * k + 0], l0, h0);
        unpack2(acc[2 * k + 1], l1, h1v);
        __half2 a = __floats2half2_rn(fmaxf(l0, 0.f), fmaxf(h0, 0.f));
        __half2 b = __floats2half2_rn(fmaxf(l1, 0.f), fmaxf(h1v, 0.f));
        // combine the two half2 into one 32-bit word each; hw[k] spans 2 ch
        hw[k] = (uint32_t)*reinterpret_cast<unsigned short*>(&a) |
                ((uint32_t)*(reinterpret_cast<unsigned short*>(&a) + 1) << 16);
        (void)b;
        // store b into the next word via second half of the pair loop:
        // handled by writing pairs directly below
        uint32_t wb = (uint32_t)*reinterpret_cast<unsigned short*>(&b) |
                ((uint32_t)*(reinterpret_cast<unsigned short*>(&b) + 1) << 16);
        hw[k] = *reinterpret_cast<uint32_t*>(&a);
        // hw holds 8 words = 16 halves = 16 channels... we need 32 channels:
        // acc has 16 pairs = 32 channels = 16 half2 words. Use two uint4s of
        // words built from consecutive acc pairs: word index = k over 0..15.
        (void)wb;
    }
    // authoritative packing: 16 half2 words, two uint4 stores
    uint32_t w16[16];
#pragma unroll
    for (int k = 0; k < 16; k++) {
        float lo, hi;
        unpack2(acc[k], lo, hi);
        __half2 h = __floats2half2_rn(fmaxf(lo, 0.f), fmaxf(hi, 0.f));
        w16[k] = *reinterpret_cast<uint32_t*>(&h);
    }
    __half* dst = g_feat_h + (size_t)p * 128 + cbase;
    reinterpret_cast<uint4*>(dst)[0] = make_uint4(w16[0], w16[1], w16[2], w16[3]);
    reinterpret_cast<uint4*>(dst)[1] = make_uint4(w16[4], w16[5], w16[6], w16[7]);
    reinterpret_cast<uint4*>(dst)[2] = make_uint4(w16[8], w16[9], w16[10], w16[11]);
    reinterpret_cast<uint4*>(dst)[3] = make_uint4(w16[12], w16[13], w16[14], w16[15]);
}

// ---------------------------------------------------------------------------
// Kernel 2: fused ball-query + fp16 feature max-pool.
// One warp per query. Phase A: scan m ascending, build index list of the
// first 64 accepted (ballot + prefix-popc into smem, no serial ffs chain).
// Phase B: half-warps gather 2 neighbor rows per iteration (16 B/lane
// LDG.128 of fp16 features), HMAX2 accumulate, shfl-combine at the end.
// ---------------------------------------------------------------------------
__global__ __launch_bounds__(1024) void group_kernel(
    const float* __restrict__ x, float* __restrict__ out)
{
    __shared__ float smem_buf[NPTS * 4];          // 32 KB: sx, reused as sout
    __shared__ uint16_t slist[32][NSAMP];         // 4 KB accepted indices
    float4* sx = reinterpret_cast<float4*>(smem_buf);

    const int b   = blockIdx.y;
    const int n0  = blockIdx.x * 32;
    const int tid = threadIdx.x;
    const float* xb = x + (size_t)b * NPTS * 3;

    for (int p = tid; p < NPTS; p += 1024) {
        const float px = xb[p * 3 + 0];
        const float py = xb[p * 3 + 1];
        const float pz = xb[p * 3 + 2];
        const float sq = px * px + py * py + pz * pz;
        sx[p] = make_float4(px, py, pz, sq);
    }
    __syncthreads();

    const int w    = tid >> 5;
    const int lane = tid & 31;
    const int n    = n0 + w;
    const float4 q = sx[n];
    const unsigned lt_mask = (1u << lane) - 1u;

    // Phase A: build accepted-index list (ascending m, cap 64)
    int count = 0;
    for (int base = 0; base < NPTS; base += 32) {
        const float4 pm = sx[base + lane];
        const float dist = q.w + pm.w -
            2.0f * (q.x * pm.x + q.y * pm.y + q.z * pm.z);
        const unsigned mask = __ballot_sync(0xffffffffu, !(dist > R2));
        const int take = min(__popc(mask), NSAMP - count);
        if ((mask >> lane) & 1u) {
            const int pos = count + __popc(mask & lt_mask);
            if (pos < count + take) slist[w][pos] = (uint16_t)(base + lane);
        }
        count += take;
        if (count >= NSAMP) break;
    }
    __syncthreads();   // all warps done with sx; smem_buf reusable as sout

    // Phase B: gather + max. lane<16 -> even list slots, lane>=16 -> odd.
    const int half = lane >> 4;
    const int lc   = lane & 15;
    const uint4* fb = reinterpret_cast<const uint4*>(
        g_feat_h + (size_t)b * NPTS * 128);
    __half2 a0 = __float2half2_rn(0.f), a1 = a0, a2 = a0, a3 = a0;

    for (int i = 0; i < count; i += 4) {
        const int l0 = i + half;
        const int l1 = i + 2 + half;
        const int m0 = slist[w][l0 < count ? l0 : 0];
        const int m1 = slist[w][l1 < count ? l1 : 0];
        const uint4 v0 = fb[m0 * 16 + lc];   // 256 B/row, 2 rows per warp-iter
        const uint4 v1 = fb[m1 * 16 + lc];
        a0 = __hmax2(a0, *reinterpret_cast<const __half2*>(&v0.x));
        a1 = __hmax2(a1, *reinterpret_cast<const __half2*>(&v0.y));
        a2 = __hmax2(a2, *reinterpret_cast<const __half2*>(&v0.z));
        a3 = __hmax2(a3, *reinterpret_cast<const __half2*>(&v0.w));
        a0 = __hmax2(a0, *reinterpret_cast<const __half2*>(&v1.x));
        a1 = __hmax2(a1, *reinterpret_cast<const __half2*>(&v1.y));
        a2 = __hmax2(a2, *reinterpret_cast<const __half2*>(&v1.z));
        a3 = __hmax2(a3, *reinterpret_cast<const __half2*>(&v1.w));
    }
    // combine the two half-warps (each holds the other's neighbors' partials)
    {
        uint32_t u;
        u = __shfl_xor_sync(0xffffffffu, *reinterpret_cast<uint32_t*>(&a0), 16);
        a0 = __hmax2(a0, *reinterpret_cast<__half2*>(&u));
        u = __shfl_xor_sync(0xffffffffu, *reinterpret_cast<uint32_t*>(&a1), 16);
        a1 = __hmax2(a1, *reinterpret_cast<__half2*>(&u));
        u = __shfl_xor_sync(0xffffffffu, *reinterpret_cast<uint32_t*>(&a2), 16);
        a2 = __hmax2(a2, *reinterpret_cast<__half2*>(&u));
        u = __shfl_xor_sync(0xffffffffu, *reinterpret_cast<uint32_t*>(&a3), 16);
        a3 = __hmax2(a3, *reinterpret_cast<__half2*>(&u));
    }

    // stage to sout[q][c] (stride 133: conflict-free transposed readback).
    // lane holds channels 8*lc .. 8*lc+7; halves store disjoint 4-ch parts.
    float* sout = smem_buf;
    {
        float* so = sout + w * 133 + 8 * lc;
        if (half == 0) {
            const float2 f0 = __half22float2(a0);
            const float2 f1 = __half22float2(a1);
            so[0] = f0.x; so[1] = f0.y; so[2] = f1.x; so[3] = f1.y;
        } else {
            const float2 f2 = __half22float2(a2);
            const float2 f3 = __half22float2(a3);
            so[4] = f2.x; so[5] = f2.y; so[6] = f3.x; so[7] = f3.y;
        }
    }
    __syncthreads();

    // out[b, c, n0+qq]: 32 consecutive n per store -> 128 B coalesced
    float* ob = out + (size_t)b * 128 * NPTS + n0;
    const int qq = tid & 31;
    const int c0 = tid >> 5;
#pragma unroll
    for (int pass = 0; pass < 4; pass++) {
        const int c = pass * 32 + c0;
        ob[(size_t)c * NPTS + qq] = sout[qq * 133 + c];
    }
}

extern "C" void kernel_launch(void* const* d_in, const int* in_sizes, int n_in,
                              void* d_out, int out_size)
{
    const float* x  = (const float*)d_in[0];   // (8, 2048, 3)
    const float* W1 = (const float*)d_in[1];   // (64, 3)
    const float* b1 = (const float*)d_in[2];   // (64,)
    const float* W2 = (const float*)d_in[3];   // (128, 64)
    const float* b2 = (const float*)d_in[4];   // (128,)
    float* out = (float*)d_out;                // (8, 128, 2048)

    feat_kernel<<<256, 256>>>(x, W1, b1, W2, b2);
    group_kernel<<<dim3(64, 8), 1024>>>(x, out);
}

// round 6
// speedup vs baseline: 1.0040x; 1.0040x over previous
#include <cuda_runtime.h>
#include <cuda_fp16.h>
#include <cstdint>

#define NPTS   2048
#define NBATCH 8
#define NSAMP  64
#define R2     0.36f

// 4 MB fp16 feature table: f[b][m][c], c = 0..127
__device__ __half g_feat_h[NBATCH * NPTS * 128];

// packed fp32x2 FMA (sm_100+): d.lo += a.lo*b.lo ; d.hi += a.hi*b.hi
__device__ __forceinline__ void ffma2(unsigned long long& d,
                                      unsigned long long a,
                                      unsigned long long b) {
    asm("fma.rn.f32x2 %0, %1, %2, %0;" : "+l"(d) : "l"(a), "l"(b));
}
__device__ __forceinline__ unsigned long long pack2(float lo, float hi) {
    unsigned long long r;
    asm("mov.b64 %0, {%1, %2};" : "=l"(r) : "f"(lo), "f"(hi));
    return r;
}
__device__ __forceinline__ void unpack2(unsigned long long v, float& lo, float& hi) {
    asm("mov.b64 {%0, %1}, %2;" : "=f"(lo), "=f"(hi) : "l"(v));
}
// half2(max(lo,0), max(hi,0)) -> 32-bit word, no address-taken locals
__device__ __forceinline__ uint32_t relu_pack_h2(unsigned long long v) {
    float lo, hi;
    unpack2(v, lo, hi);
    union { __half2 h; uint32_t u; } cv;
    cv.h = __floats2half2_rn(fmaxf(lo, 0.f), fmaxf(hi, 0.f));
    return cv.u;
}

// ---------------------------------------------------------------------------
// Kernel 1: f[b,m,:] = relu(W2*relu(W1*x+b1)+b2), fp16 output.
// Warp = 32 points (lanes) x one 32-channel quarter. Layer 2 uses FFMA2:
// acc[k] holds channel pair (cbase+2k, cbase+2k+1) in full fp32. W2 is
// transposed in smem so one broadcast LDS.128 feeds two channel pairs.
// ---------------------------------------------------------------------------
__global__ __launch_bounds__(256, 2) void feat_kernel(
    const float* __restrict__ x, const float* __restrict__ W1,
    const float* __restrict__ b1, const float* __restrict__ W2,
    const float* __restrict__ b2)
{
    __shared__ float sW1[64 * 3];
    __shared__ float sb1[64];
    __shared__ float sb2[128];
    __shared__ float sW2t[64 * 128];   // [o][c] = W2[c][o], 32 KB

    const int tid = threadIdx.x;
    for (int i = tid; i < 192; i += 256) sW1[i] = W1[i];
    for (int i = tid; i < 64;  i += 256) sb1[i] = b1[i];
    for (int i = tid; i < 128; i += 256) sb2[i] = b2[i];
    for (int i = tid; i < 64 * 128; i += 256) {
        const int o = i >> 7, c = i & 127;
        sW2t[o * 128 + c] = W2[c * 64 + o];
    }
    __syncthreads();

    const int lane    = tid & 31;
    const int gwarp   = blockIdx.x * 8 + (tid >> 5);  // 0..2047
    const int quarter = gwarp & 3;
    const int cbase   = quarter * 32;
    const int p       = (gwarp >> 2) * 32 + lane;     // 0..16383

    const float x0 = x[p * 3 + 0];
    const float x1 = x[p * 3 + 1];
    const float x2 = x[p * 3 + 2];

    float h1[64];
#pragma unroll
    for (int o = 0; o < 64; o++) {
        float v = sb1[o];
        v = fmaf(sW1[o * 3 + 0], x0, v);
        v = fmaf(sW1[o * 3 + 1], x1, v);
        v = fmaf(sW1[o * 3 + 2], x2, v);
        h1[o] = fmaxf(v, 0.0f);
    }

    unsigned long long acc[16];
    const unsigned long long* b2p =
        reinterpret_cast<const unsigned long long*>(sb2 + cbase);
#pragma unroll
    for (int k = 0; k < 16; k++) acc[k] = b2p[k];

#pragma unroll 2
    for (int o = 0; o < 64; o++) {
        const unsigned long long hh = pack2(h1[o], h1[o]);
        const ulonglong2* wrow =
            reinterpret_cast<const ulonglong2*>(sW2t + o * 128 + cbase);
#pragma unroll
        for (int j = 0; j < 8; j++) {
            const ulonglong2 w = wrow[j];   // LDS.128, warp-broadcast
            ffma2(acc[2 * j + 0], w.x, hh);
            ffma2(acc[2 * j + 1], w.y, hh);
        }
    }

    // relu -> fp16: word k = half2(channels cbase+2k, cbase+2k+1)
    __half* dst = g_feat_h + (size_t)p * 128 + cbase;
#pragma unroll
    for (int g = 0; g < 4; g++) {
        uint4 wv;
        wv.x = relu_pack_h2(acc[4 * g + 0]);
        wv.y = relu_pack_h2(acc[4 * g + 1]);
        wv.z = relu_pack_h2(acc[4 * g + 2]);
        wv.w = relu_pack_h2(acc[4 * g + 3]);
        reinterpret_cast<uint4*>(dst)[g] = wv;
    }
}

// ---------------------------------------------------------------------------
// Kernel 2: fused ball-query + fp16 feature max-pool.
// One warp per query. Phase A: ascending scan, ballot + prefix-popc builds
// the first-64-accepted index list in smem (matches reference semantics).
// Phase B: half-warps gather 2 rows per LDG step; fast path for count==64
// fully unrolled with 4 LDG.128 in flight. shfl-combine, staged stores.
// ---------------------------------------------------------------------------
__global__ __launch_bounds__(1024) void group_kernel(
    const float* __restrict__ x, float* __restrict__ out)
{
    __shared__ float4   sx[NPTS];          // 32 KB
    __shared__ float    sout[32 * 133];    // 17 KB (133: conflict-free rdbk)
    __shared__ uint16_t slist[32][NSAMP];  // 4 KB

    const int b   = blockIdx.y;
    const int n0  = blockIdx.x * 32;
    const int tid = threadIdx.x;
    const float* xb = x + (size_t)b * NPTS * 3;

    for (int p = tid; p < NPTS; p += 1024) {
        const float px = xb[p * 3 + 0];
        const float py = xb[p * 3 + 1];
        const float pz = xb[p * 3 + 2];
        sx[p] = make_float4(px, py, pz, px * px + py * py + pz * pz);
    }
    __syncthreads();

    const int w    = tid >> 5;
    const int lane = tid & 31;
    const float4 q = sx[n0 + w];
    const unsigned lt_mask = (1u << lane) - 1u;

    // Phase A
    int count = 0;
    for (int base = 0; base < NPTS; base += 32) {
        const float4 pm = sx[base + lane];
        const float dist = q.w + pm.w -
            2.0f * (q.x * pm.x + q.y * pm.y + q.z * pm.z);
        const unsigned mask = __ballot_sync(0xffffffffu, !(dist > R2));
        const int take = min(__popc(mask), NSAMP - count);
        if ((mask >> lane) & 1u) {
            const int pos = count + __popc(mask & lt_mask);
            if (pos < count + take) slist[w][pos] = (uint16_t)(base + lane);
        }
        count += take;
        if (count >= NSAMP) break;
    }
    __syncwarp();

    // Phase B
    const int half = lane >> 4;            // 0: even list slots, 1: odd
    const int lc   = lane & 15;            // 16 B chunk within 256 B row
    const uint4* fb = reinterpret_cast<const uint4*>(
        g_feat_h + (size_t)b * NPTS * 128);
    __half2 a0 = __float2half2_rn(0.f), a1 = a0, a2 = a0, a3 = a0;

    if (count == NSAMP) {
#pragma unroll
        for (int i = 0; i < NSAMP; i += 8) {
            const int m0 = slist[w][i + 0 + half];
            const int m1 = slist[w][i + 2 + half];
            const int m2 = slist[w][i + 4 + half];
            const int m3 = slist[w][i + 6 + half];
            const uint4 v0 = fb[m0 * 16 + lc];
            const uint4 v1 = fb[m1 * 16 + lc];
            const uint4 v2 = fb[m2 * 16 + lc];
            const uint4 v3 = fb[m3 * 16 + lc];
            a0 = __hmax2(a0, *reinterpret_cast<const __half2*>(&v0.x));
            a1 = __hmax2(a1, *reinterpret_cast<const __half2*>(&v0.y));
            a2 = __hmax2(a2, *reinterpret_cast<const __half2*>(&v0.z));
            a3 = __hmax2(a3, *reinterpret_cast<const __half2*>(&v0.w));
            a0 = __hmax2(a0, *reinterpret_cast<const __half2*>(&v1.x));
            a1 = __hmax2(a1, *reinterpret_cast<const __half2*>(&v1.y));
            a2 = __hmax2(a2, *reinterpret_cast<const __half2*>(&v1.z));
            a3 = __hmax2(a3, *reinterpret_cast<const __half2*>(&v1.w));
            a0 = __hmax2(a0, *reinterpret_cast<const __half2*>(&v2.x));
            a1 = __hmax2(a1, *reinterpret_cast<const __half2*>(&v2.y));
            a2 = __hmax2(a2, *reinterpret_cast<const __half2*>(&v2.z));
            a3 = __hmax2(a3, *reinterpret_cast<const __half2*>(&v2.w));
            a0 = __hmax2(a0, *reinterpret_cast<const __half2*>(&v3.x));
            a1 = __hmax2(a1, *reinterpret_cast<const __half2*>(&v3.y));
            a2 = __hmax2(a2, *reinterpret_cast<const __half2*>(&v3.z));
            a3 = __hmax2(a3, *reinterpret_cast<const __half2*>(&v3.w));
        }
    } else {
        for (int i = 0; i < count; i += 4) {
            const int l0 = i + half;
            const int l1 = i + 2 + half;
            const int m0 = slist[w][l0 < count ? l0 : 0];
            const int m1 = slist[w][l1 < count ? l1 : 0];
            const uint4 v0 = fb[m0 * 16 + lc];
            const uint4 v1 = fb[m1 * 16 + lc];
            a0 = __hmax2(a0, *reinterpret_cast<const __half2*>(&v0.x));
            a1 = __hmax2(a1, *reinterpret_cast<const __half2*>(&v0.y));
            a2 = __hmax2(a2, *reinterpret_cast<const __half2*>(&v0.z));
            a3 = __hmax2(a3, *reinterpret_cast<const __half2*>(&v0.w));
            a0 = __hmax2(a0, *reinterpret_cast<const __half2*>(&v1.x));
            a1 = __hmax2(a1, *reinterpret_cast<const __half2*>(&v1.y));
            a2 = __hmax2(a2, *reinterpret_cast<const __half2*>(&v1.z));
            a3 = __hmax2(a3, *reinterpret_cast<const __half2*>(&v1.w));
        }
    }

    // combine the two half-warps (each holds the other half's partials)
    {
        uint32_t u;
        u = __shfl_xor_sync(0xffffffffu, *reinterpret_cast<uint32_t*>(&a0), 16);
        a0 = __hmax2(a0, *reinterpret_cast<__half2*>(&u));
        u = __shfl_xor_sync(0xffffffffu, *reinterpret_cast<uint32_t*>(&a1), 16);
        a1 = __hmax2(a1, *reinterpret_cast<__half2*>(&u));
        u = __shfl_xor_sync(0xffffffffu, *reinterpret_cast<uint32_t*>(&a2), 16);
        a2 = __hmax2(a2, *reinterpret_cast<__half2*>(&u));
        u = __shfl_xor_sync(0xffffffffu, *reinterpret_cast<uint32_t*>(&a3), 16);
        a3 = __hmax2(a3, *reinterpret_cast<__half2*>(&u));
    }

    // stage sout[q][c]: lane lc holds channels 8*lc..8*lc+7; halves write
    // disjoint 4-channel parts -> no races
    {
        float* so = sout + w * 133 + 8 * lc;
        if (half == 0) {
            const float2 f0 = __half22float2(a0);
            const float2 f1 = __half22float2(a1);
            so[0] = f0.x; so[1] = f0.y; so[2] = f1.x; so[3] = f1.y;
        } else {
            const float2 f2 = __half22float2(a2);
            const float2 f3 = __half22float2(a3);
            so[4] = f2.x; so[5] = f2.y; so[6] = f3.x; so[7] = f3.y;
        }
    }
    __syncthreads();

    // out[b, c, n0+qq]: 32 consecutive n per store -> 128 B coalesced
    float* ob = out + (size_t)b * 128 * NPTS + n0;
    const int qq = tid & 31;
    const int c0 = tid >> 5;
#pragma unroll
    for (int pass = 0; pass < 4; pass++) {
        const int c = pass * 32 + c0;
        ob[(size_t)c * NPTS + qq] = sout[qq * 133 + c];
    }
}

extern "C" void kernel_launch(void* const* d_in, const int* in_sizes, int n_in,
                              void* d_out, int out_size)
{
    const float* x  = (const float*)d_in[0];   // (8, 2048, 3)
    const float* W1 = (const float*)d_in[1];   // (64, 3)
    const float* b1 = (const float*)d_in[2];   // (64,)
    const float* W2 = (const float*)d_in[3];   // (128, 64)
    const float* b2 = (const float*)d_in[4];   // (128,)
    float* out = (float*)d_out;                // (8, 128, 2048)

    feat_kernel<<<256, 256>>>(x, W1, b1, W2, b2);
    group_kernel<<<dim3(64, 8), 1024>>>(x, out);
}

// round 8
// speedup vs baseline: 1.1488x; 1.1442x over previous
#include <cuda_runtime.h>
#include <cuda_fp16.h>
#include <cstdint>

#define NPTS   2048
#define NBATCH 8
#define NSAMP  64
#define R2     0.36f

// 4 MB fp16 feature table: f[b][m][c], c = 0..127
__device__ __half g_feat_h[NBATCH * NPTS * 128];

// packed fp32x2 FMA (sm_100+): d.lo += a.lo*b.lo ; d.hi += a.hi*b.hi
__device__ __forceinline__ void ffma2(unsigned long long& d,
                                      unsigned long long a,
                                      unsigned long long b) {
    asm("fma.rn.f32x2 %0, %1, %2, %0;" : "+l"(d) : "l"(a), "l"(b));
}
__device__ __forceinline__ unsigned long long pack2(float lo, float hi) {
    unsigned long long r;
    asm("mov.b64 %0, {%1, %2};" : "=l"(r) : "f"(lo), "f"(hi));
    return r;
}
__device__ __forceinline__ void unpack2(unsigned long long v, float& lo, float& hi) {
    asm("mov.b64 {%0, %1}, %2;" : "=f"(lo), "=f"(hi) : "l"(v));
}
__device__ __forceinline__ uint32_t relu_pack_h2(unsigned long long v) {
    float lo, hi;
    unpack2(v, lo, hi);
    union { __half2 h; uint32_t u; } cv;
    cv.h = __floats2half2_rn(fmaxf(lo, 0.f), fmaxf(hi, 0.f));
    return cv.u;
}

// W2 transposed in smem with pad-132 rows: row o = 132 floats (528 B,
// 16B-aligned), [o][c] = W2[c][o].
#define W2T_STRIDE 132

// ---------------------------------------------------------------------------
// Kernel 1: f[b,m,:] = relu(W2*relu(W1*x+b1)+b2), fp16 output.
// Warp = 32 points (lanes) x one 32-channel quarter. Layer 2 uses FFMA2:
// acc[k] holds channel pair (cbase+2k, cbase+2k+1) in full fp32.
// W2 transpose preamble: o = i&63 (fast) -> GLOBAL read W2[c*64+o] is
// coalesced (o is W2's fast axis); smem write is a one-time 4-way conflict.
// ---------------------------------------------------------------------------
__global__ __launch_bounds__(256, 2) void feat_kernel(
    const float* __restrict__ x, const float* __restrict__ W1,
    const float* __restrict__ b1, const float* __restrict__ W2,
    const float* __restrict__ b2)
{
    __shared__ float sW1[64 * 3];
    __shared__ float sb1[64];
    __shared__ float sb2[128];
    __shared__ float sW2t[64 * W2T_STRIDE];   // ~33.8 KB

    const int tid = threadIdx.x;
    for (int i = tid; i < 192; i += 256) sW1[i] = W1[i];
    for (int i = tid; i < 64;  i += 256) sb1[i] = b1[i];
    for (int i = tid; i < 128; i += 256) sb2[i] = b2[i];
#pragma unroll
    for (int k = 0; k < 32; k++) {            // 8192 = 32 * 256
        const int i = k * 256 + tid;
        const int o = i & 63;                 // fast axis -> coalesced read
        const int c = i >> 6;
        sW2t[o * W2T_STRIDE + c] = W2[c * 64 + o];
    }
    __syncthreads();

    const int lane    = tid & 31;
    const int gwarp   = blockIdx.x * 8 + (tid >> 5);  // 0..2047
    const int quarter = gwarp & 3;
    const int cbase   = quarter * 32;
    const int p       = (gwarp >> 2) * 32 + lane;     // 0..16383

    const float x0 = x[p * 3 + 0];
    const float x1 = x[p * 3 + 1];
    const float x2 = x[p * 3 + 2];

    float h1[64];
#pragma unroll
    for (int o = 0; o < 64; o++) {
        float v = sb1[o];
        v = fmaf(sW1[o * 3 + 0], x0, v);
        v = fmaf(sW1[o * 3 + 1], x1, v);
        v = fmaf(sW1[o * 3 + 2], x2, v);
        h1[o] = fmaxf(v, 0.0f);
    }

    unsigned long long acc[16];
    const unsigned long long* b2p =
        reinterpret_cast<const unsigned long long*>(sb2 + cbase);
#pragma unroll
    for (int k = 0; k < 16; k++) acc[k] = b2p[k];

#pragma unroll 2
    for (int o = 0; o < 64; o++) {
        const unsigned long long hh = pack2(h1[o], h1[o]);
        const ulonglong2* wrow =
            reinterpret_cast<const ulonglong2*>(sW2t + o * W2T_STRIDE + cbase);
#pragma unroll
        for (int j = 0; j < 8; j++) {
            const ulonglong2 w = wrow[j];   // LDS.128, warp-broadcast
            ffma2(acc[2 * j + 0], w.x, hh);
            ffma2(acc[2 * j + 1], w.y, hh);
        }
    }

    // relu -> fp16: word k = half2(channels cbase+2k, cbase+2k+1)
    __half* dst = g_feat_h + (size_t)p * 128 + cbase;
#pragma unroll
    for (int g = 0; g < 4; g++) {
        uint4 wv;
        wv.x = relu_pack_h2(acc[4 * g + 0]);
        wv.y = relu_pack_h2(acc[4 * g + 1]);
        wv.z = relu_pack_h2(acc[4 * g + 2]);
        wv.w = relu_pack_h2(acc[4 * g + 3]);
        reinterpret_cast<uint4*>(dst)[g] = wv;
    }
}

// ---------------------------------------------------------------------------
// Kernel 2: fused ball-query + fp16 feature max-pool.
// One warp per query. Phase A: ascending scan, ballot + prefix-popc builds
// the first-64-accepted index list in smem (reference semantics).
// Phase B: half-warps gather 2 rows per LDG; indices come 8-at-a-time via
// one LDS.128 + shift-extract. Fast path (count==64) fully unrolled.
// ---------------------------------------------------------------------------
__global__ __launch_bounds__(1024, 2) void group_kernel(
    const float* __restrict__ x, float* __restrict__ out)
{
    __shared__ float4   sx[NPTS];          // 32 KB
    __shared__ float    sout[32 * 133];    // 17 KB (conflict-free readback)
    __shared__ __align__(16) uint16_t slist[32][NSAMP];  // 4 KB, 128 B rows

    const int b   = blockIdx.y;
    const int n0  = blockIdx.x * 32;
    const int tid = threadIdx.x;
    const float* xb = x + (size_t)b * NPTS * 3;

    for (int p = tid; p < NPTS; p += 1024) {
        const float px = xb[p * 3 + 0];
        const float py = xb[p * 3 + 1];
        const float pz = xb[p * 3 + 2];
        sx[p] = make_float4(px, py, pz, px * px + py * py + pz * pz);
    }
    __syncthreads();

    const int w    = tid >> 5;
    const int lane = tid & 31;
    const float4 q = sx[n0 + w];
    const unsigned lt_mask = (1u << lane) - 1u;

    // Phase A
    int count = 0;
    for (int base = 0; base < NPTS; base += 32) {
        const float4 pm = sx[base + lane];
        const float dist = q.w + pm.w -
            2.0f * (q.x * pm.x + q.y * pm.y + q.z * pm.z);
        const unsigned mask = __ballot_sync(0xffffffffu, !(dist > R2));
        const int take = min(__popc(mask), NSAMP - count);
        if ((mask >> lane) & 1u) {
            const int pos = count + __popc(mask & lt_mask);
            if (pos < count + take) slist[w][pos] = (uint16_t)(base + lane);
        }
        count += take;
        if (count >= NSAMP) break;
    }
    __syncwarp();

    // Phase B
    const int half = lane >> 4;            // 0: even list slots, 1: odd
    const int lc   = lane & 15;            // 16 B chunk within 256 B row
    const int sh   = half * 16;            // extract shift (lane-uniform/half)
    const uint4* fb = reinterpret_cast<const uint4*>(
        g_feat_h + (size_t)b * NPTS * 128);
    const uint4* sl = reinterpret_cast<const uint4*>(slist[w]);
    __half2 a0 = __float2half2_rn(0.f), a1 = a0, a2 = a0, a3 = a0;

    if (count == NSAMP) {
#pragma unroll
        for (int g = 0; g < NSAMP / 8; g++) {
            const uint4 sv = sl[g];        // 8 indices in one LDS.128
            const int m0 = (sv.x >> sh) & 0xffff;
            const int m1 = (sv.y >> sh) & 0xffff;
            const int m2 = (sv.z >> sh) & 0xffff;
            const int m3 = (sv.w >> sh) & 0xffff;
            const uint4 v0 = fb[m0 * 16 + lc];
            const uint4 v1 = fb[m1 * 16 + lc];
            const uint4 v2 = fb[m2 * 16 + lc];
            const uint4 v3 = fb[m3 * 16 + lc];
            a0 = __hmax2(a0, *reinterpret_cast<const __half2*>(&v0.x));
            a1 = __hmax2(a1, *reinterpret_cast<const __half2*>(&v0.y));
            a2 = __hmax2(a2, *reinterpret_cast<const __half2*>(&v0.z));
            a3 = __hmax2(a3, *reinterpret_cast<const __half2*>(&v0.w));
            a0 = __hmax2(a0, *reinterpret_cast<const __half2*>(&v1.x));
            a1 = __hmax2(a1, *reinterpret_cast<const __half2*>(&v1.y));
            a2 = __hmax2(a2, *reinterpret_cast<const __half2*>(&v1.z));
            a3 = __hmax2(a3, *reinterpret_cast<const __half2*>(&v1.w));
            a0 = __hmax2(a0, *reinterpret_cast<const __half2*>(&v2.x));
            a1 = __hmax2(a1, *reinterpret_cast<const __half2*>(&v2.y));
            a2 = __hmax2(a2, *reinterpret_cast<const __half2*>(&v2.z));
            a3 = __hmax2(a3, *reinterpret_cast<const __half2*>(&v2.w));
            a0 = __hmax2(a0, *reinterpret_cast<const __half2*>(&v3.x));
            a1 = __hmax2(a1, *reinterpret_cast<const __half2*>(&v3.y));
            a2 = __hmax2(a2, *reinterpret_cast<const __half2*>(&v3.z));
            a3 = __hmax2(a3, *reinterpret_cast<const __half2*>(&v3.w));
        }
    } else {
        for (int i = 0; i < count; i += 4) {
            const int l0 = i + half;
            const int l1 = i + 2 + half;
            const int m0 = slist[w][l0 < count ? l0 : 0];
            const int m1 = slist[w][l1 < count ? l1 : 0];
            const uint4 v0 = fb[m0 * 16 + lc];
            const uint4 v1 = fb[m1 * 16 + lc];
            a0 = __hmax2(a0, *reinterpret_cast<const __half2*>(&v0.x));
            a1 = __hmax2(a1, *reinterpret_cast<const __half2*>(&v0.y));
            a2 = __hmax2(a2, *reinterpret_cast<const __half2*>(&v0.z));
            a3 = __hmax2(a3, *reinterpret_cast<const __half2*>(&v0.w));
            a0 = __hmax2(a0, *reinterpret_cast<const __half2*>(&v1.x));
            a1 = __hmax2(a1, *reinterpret_cast<const __half2*>(&v1.y));
            a2 = __hmax2(a2, *reinterpret_cast<const __half2*>(&v1.z));
            a3 = __hmax2(a3, *reinterpret_cast<const __half2*>(&v1.w));
        }
    }

    // combine the two half-warps
    {
        uint32_t u;
        u = __shfl_xor_sync(0xffffffffu, *reinterpret_cast<uint32_t*>(&a0), 16);
        a0 = __hmax2(a0, *reinterpret_cast<__half2*>(&u));
        u = __shfl_xor_sync(0xffffffffu, *reinterpret_cast<uint32_t*>(&a1), 16);
        a1 = __hmax2(a1, *reinterpret_cast<__half2*>(&u));
        u = __shfl_xor_sync(0xffffffffu, *reinterpret_cast<uint32_t*>(&a2), 16);
        a2 = __hmax2(a2, *reinterpret_cast<__half2*>(&u));
        u = __shfl_xor_sync(0xffffffffu, *reinterpret_cast<uint32_t*>(&a3), 16);
        a3 = __hmax2(a3, *reinterpret_cast<__half2*>(&u));
    }

    // stage sout[q][c]: lane lc holds channels 8*lc..8*lc+7; halves write
    // disjoint 4-channel parts
    {
        float* so = sout + w * 133 + 8 * lc;
        if (half == 0) {
            const float2 f0 = __half22float2(a0);
            const float2 f1 = __half22float2(a1);
            so[0] = f0.x; so[1] = f0.y; so[2] = f1.x; so[3] = f1.y;
        } else {
            const float2 f2 = __half22float2(a2);
            const float2 f3 = __half22float2(a3);
            so[4] = f2.x; so[5] = f2.y; so[6] = f3.x; so[7] = f3.y;
        }
    }
    __syncthreads();

    // out[b, c, n0+qq]: 32 consecutive n per store -> 128 B coalesced
    float* ob = out + (size_t)b * 128 * NPTS + n0;
    const int qq = tid & 31;
    const int c0 = tid >> 5;
#pragma unroll
    for (int pass = 0; pass < 4; pass++) {
        const int c = pass * 32 + c0;
        ob[(size_t)c * NPTS + qq] = sout[qq * 133 + c];
    }
}

extern "C" void kernel_launch(void* const* d_in, const int* in_sizes, int n_in,
                              void* d_out, int out_size)
{
    const float* x  = (const float*)d_in[0];   // (8, 2048, 3)
    const float* W1 = (const float*)d_in[1];   // (64, 3)
    const float* b1 = (const float*)d_in[2];   // (64,)
    const float* W2 = (const float*)d_in[3];   // (128, 64)
    const float* b2 = (const float*)d_in[4];   // (128,)
    float* out = (float*)d_out;                // (8, 128, 2048)

    feat_kernel<<<256, 256>>>(x, W1, b1, W2, b2);
    group_kernel<<<dim3(64, 8), 1024>>>(x, out);
}

// round 11
// speedup vs baseline: 1.2169x; 1.0593x over previous
#include <cuda_runtime.h>
#include <cuda_fp16.h>
#include <cstdint>

#define NPTS   2048
#define NBATCH 8
#define NSAMP  64
#define R2     0.36f

// 4 MB fp16 feature table: f[b][m][c], c = 0..127
__device__ __half g_feat_h[NBATCH * NPTS * 128];

// packed fp32x2 FMA (sm_100+): d.lo += a.lo*b.lo ; d.hi += a.hi*b.hi
__device__ __forceinline__ void ffma2(unsigned long long& d,
                                      unsigned long long a,
                                      unsigned long long b) {
    asm("fma.rn.f32x2 %0, %1, %2, %0;" : "+l"(d) : "l"(a), "l"(b));
}
__device__ __forceinline__ unsigned long long pack2(float lo, float hi) {
    unsigned long long r;
    asm("mov.b64 %0, {%1, %2};" : "=l"(r) : "f"(lo), "f"(hi));
    return r;
}
__device__ __forceinline__ void unpack2(unsigned long long v, float& lo, float& hi) {
    asm("mov.b64 {%0, %1}, %2;" : "=f"(lo), "=f"(hi) : "l"(v));
}
__device__ __forceinline__ uint32_t relu_pack_h2(unsigned long long v) {
    float lo, hi;
    unpack2(v, lo, hi);
    union { __half2 h; uint32_t u; } cv;
    cv.h = __floats2half2_rn(fmaxf(lo, 0.f), fmaxf(hi, 0.f));
    return cv.u;
}

// W2 transposed in smem, pad-132 rows (528 B, 16B-aligned): [o][c] = W2[c][o]
#define W2T_STRIDE 132

// ---------------------------------------------------------------------------
// Kernel 1: f[b,m,:] = relu(W2*relu(W1*x+b1)+b2), fp16 output.
// 128 blocks x 512 threads = single wave. Warp = 32 points x one 32-channel
// quarter; FFMA2 keeps channel pairs in fp32. The o-loop is split into two
// 32-wide chunks so only 32 h1 values are live at once (~85 regs, no spills
// -- h1[64]+acc[16x64b] was spilling at R8).
// ---------------------------------------------------------------------------
__global__ __launch_bounds__(512, 1) void feat_kernel(
    const float* __restrict__ x, const float* __restrict__ W1,
    const float* __restrict__ b1, const float* __restrict__ W2,
    const float* __restrict__ b2)
{
    __shared__ float sW1[64 * 3];
    __shared__ float sb1[64];
    __shared__ float sb2[128];
    __shared__ float sW2t[64 * W2T_STRIDE];   // ~33.8 KB

    const int tid = threadIdx.x;
    for (int i = tid; i < 192; i += 512) sW1[i] = W1[i];
    for (int i = tid; i < 64;  i += 512) sb1[i] = b1[i];
    for (int i = tid; i < 128; i += 512) sb2[i] = b2[i];
#pragma unroll
    for (int k = 0; k < 16; k++) {            // 8192 = 16 * 512
        const int i = k * 512 + tid;
        const int o = i & 63;                 // fast axis -> coalesced read
        const int c = i >> 6;
        sW2t[o * W2T_STRIDE + c] = W2[c * 64 + o];
    }
    __syncthreads();

    const int lane    = tid & 31;
    const int gwarp   = blockIdx.x * 16 + (tid >> 5); // 0..2047
    const int quarter = gwarp & 3;
    const int cbase   = quarter * 32;
    const int p       = (gwarp >> 2) * 32 + lane;     // 0..16383

    const float x0 = x[p * 3 + 0];
    const float x1 = x[p * 3 + 1];
    const float x2 = x[p * 3 + 2];

    unsigned long long acc[16];
    const unsigned long long* b2p =
        reinterpret_cast<const unsigned long long*>(sb2 + cbase);
#pragma unroll
    for (int k = 0; k < 16; k++) acc[k] = b2p[k];

#pragma unroll 1
    for (int och = 0; och < 2; och++) {
        const int obase = och * 32;
        float h1[32];
#pragma unroll
        for (int oo = 0; oo < 32; oo++) {
            const int o = obase + oo;
            float v = sb1[o];
            v = fmaf(sW1[o * 3 + 0], x0, v);
            v = fmaf(sW1[o * 3 + 1], x1, v);
            v = fmaf(sW1[o * 3 + 2], x2, v);
            h1[oo] = fmaxf(v, 0.0f);
        }
#pragma unroll 2
        for (int oo = 0; oo < 32; oo++) {
            const unsigned long long hh = pack2(h1[oo], h1[oo]);
            const ulonglong2* wrow = reinterpret_cast<const ulonglong2*>(
                sW2t + (obase + oo) * W2T_STRIDE + cbase);
#pragma unroll
            for (int j = 0; j < 8; j++) {
                const ulonglong2 w = wrow[j];   // LDS.128, warp-broadcast
                ffma2(acc[2 * j + 0], w.x, hh);
                ffma2(acc[2 * j + 1], w.y, hh);
            }
        }
    }

    // relu -> fp16: word k = half2(channels cbase+2k, cbase+2k+1)
    __half* dst = g_feat_h + (size_t)p * 128 + cbase;
#pragma unroll
    for (int g = 0; g < 4; g++) {
        uint4 wv;
        wv.x = relu_pack_h2(acc[4 * g + 0]);
        wv.y = relu_pack_h2(acc[4 * g + 1]);
        wv.z = relu_pack_h2(acc[4 * g + 2]);
        wv.w = relu_pack_h2(acc[4 * g + 3]);
        reinterpret_cast<uint4*>(dst)[g] = wv;
    }
}

// ---------------------------------------------------------------------------
// Kernel 2: fused ball-query + fp16 feature max-pool. (R6 form: fastest
// measured, 24.2us. Scalar uint16 index LDS -- the LDS.128+shift variant
// regressed by trading LDS slots for scarcer ALU slots.)
// ---------------------------------------------------------------------------
__global__ __launch_bounds__(1024) void group_kernel(
    const float* __restrict__ x, float* __restrict__ out)
{
    __shared__ float4   sx[NPTS];          // 32 KB
    __shared__ float    sout[32 * 133];    // 17 KB (conflict-free readback)
    __shared__ uint16_t slist[32][NSAMP];  // 4 KB

    const int b   = blockIdx.y;
    const int n0  = blockIdx.x * 32;
    const int tid = threadIdx.x;
    const float* xb = x + (size_t)b * NPTS * 3;

    for (int p = tid; p < NPTS; p += 1024) {
        const float px = xb[p * 3 + 0];
        const float py = xb[p * 3 + 1];
        const float pz = xb[p * 3 + 2];
        sx[p] = make_float4(px, py, pz, px * px + py * py + pz * pz);
    }
    __syncthreads();

    const int w    = tid >> 5;
    const int lane = tid & 31;
    const float4 q = sx[n0 + w];
    const unsigned lt_mask = (1u << lane) - 1u;

    // Phase A: first-64-accepted index list (ascending m, reference order)
    int count = 0;
    for (int base = 0; base < NPTS; base += 32) {
        const float4 pm = sx[base + lane];
        const float dist = q.w + pm.w -
            2.0f * (q.x * pm.x + q.y * pm.y + q.z * pm.z);
        const unsigned mask = __ballot_sync(0xffffffffu, !(dist > R2));
        const int take = min(__popc(mask), NSAMP - count);
        if ((mask >> lane) & 1u) {
            const int pos = count + __popc(mask & lt_mask);
            if (pos < count + take) slist[w][pos] = (uint16_t)(base + lane);
        }
        count += take;
        if (count >= NSAMP) break;
    }
    __syncwarp();

    // Phase B: half-warps gather 2 rows per LDG.128 step
    const int half = lane >> 4;
    const int lc   = lane & 15;
    const uint4* fb = reinterpret_cast<const uint4*>(
        g_feat_h + (size_t)b * NPTS * 128);
    __half2 a0 = __float2half2_rn(0.f), a1 = a0, a2 = a0, a3 = a0;

    if (count == NSAMP) {
#pragma unroll
        for (int i = 0; i < NSAMP; i += 8) {
            const int m0 = slist[w][i + 0 + half];
            const int m1 = slist[w][i + 2 + half];
            const int m2 = slist[w][i + 4 + half];
            const int m3 = slist[w][i + 6 + half];
            const uint4 v0 = fb[m0 * 16 + lc];
            const uint4 v1 = fb[m1 * 16 + lc];
            const uint4 v2 = fb[m2 * 16 + lc];
            const uint4 v3 = fb[m3 * 16 + lc];
            a0 = __hmax2(a0, *reinterpret_cast<const __half2*>(&v0.x));
            a1 = __hmax2(a1, *reinterpret_cast<const __half2*>(&v0.y));
            a2 = __hmax2(a2, *reinterpret_cast<const __half2*>(&v0.z));
            a3 = __hmax2(a3, *reinterpret_cast<const __half2*>(&v0.w));
            a0 = __hmax2(a0, *reinterpret_cast<const __half2*>(&v1.x));
            a1 = __hmax2(a1, *reinterpret_cast<const __half2*>(&v1.y));
            a2 = __hmax2(a2, *reinterpret_cast<const __half2*>(&v1.z));
            a3 = __hmax2(a3, *reinterpret_cast<const __half2*>(&v1.w));
            a0 = __hmax2(a0, *reinterpret_cast<const __half2*>(&v2.x));
            a1 = __hmax2(a1, *reinterpret_cast<const __half2*>(&v2.y));
            a2 = __hmax2(a2, *reinterpret_cast<const __half2*>(&v2.z));
            a3 = __hmax2(a3, *reinterpret_cast<const __half2*>(&v2.w));
            a0 = __hmax2(a0, *reinterpret_cast<const __half2*>(&v3.x));
            a1 = __hmax2(a1, *reinterpret_cast<const __half2*>(&v3.y));
            a2 = __hmax2(a2, *reinterpret_cast<const __half2*>(&v3.z));
            a3 = __hmax2(a3, *reinterpret_cast<const __half2*>(&v3.w));
        }
    } else {
        for (int i = 0; i < count; i += 4) {
            const int l0 = i + half;
            const int l1 = i + 2 + half;
            const int m0 = slist[w][l0 < count ? l0 : 0];
            const int m1 = slist[w][l1 < count ? l1 : 0];
            const uint4 v0 = fb[m0 * 16 + lc];
            const uint4 v1 = fb[m1 * 16 + lc];
            a0 = __hmax2(a0, *reinterpret_cast<const __half2*>(&v0.x));
            a1 = __hmax2(a1, *reinterpret_cast<const __half2*>(&v0.y));
            a2 = __hmax2(a2, *reinterpret_cast<const __half2*>(&v0.z));
            a3 = __hmax2(a3, *reinterpret_cast<const __half2*>(&v0.w));
            a0 = __hmax2(a0, *reinterpret_cast<const __half2*>(&v1.x));
            a1 = __hmax2(a1, *reinterpret_cast<const __half2*>(&v1.y));
            a2 = __hmax2(a2, *reinterpret_cast<const __half2*>(&v1.z));
            a3 = __hmax2(a3, *reinterpret_cast<const __half2*>(&v1.w));
        }
    }

    // combine the two half-warps
    {
        uint32_t u;
        u = __shfl_xor_sync(0xffffffffu, *reinterpret_cast<uint32_t*>(&a0), 16);
        a0 = __hmax2(a0, *reinterpret_cast<__half2*>(&u));
        u = __shfl_xor_sync(0xffffffffu, *reinterpret_cast<uint32_t*>(&a1), 16);
        a1 = __hmax2(a1, *reinterpret_cast<__half2*>(&u));
        u = __shfl_xor_sync(0xffffffffu, *reinterpret_cast<uint32_t*>(&a2), 16);
        a2 = __hmax2(a2, *reinterpret_cast<__half2*>(&u));
        u = __shfl_xor_sync(0xffffffffu, *reinterpret_cast<uint32_t*>(&a3), 16);
        a3 = __hmax2(a3, *reinterpret_cast<__half2*>(&u));
    }

    // stage sout[q][c]: lane lc holds channels 8*lc..8*lc+7; halves write
    // disjoint 4-channel parts
    {
        float* so = sout + w * 133 + 8 * lc;
        if (half == 0) {
            const float2 f0 = __half22float2(a0);
            const float2 f1 = __half22float2(a1);
            so[0] = f0.x; so[1] = f0.y; so[2] = f1.x; so[3] = f1.y;
        } else {
            const float2 f2 = __half22float2(a2);
            const float2 f3 = __half22float2(a3);
            so[4] = f2.x; so[5] = f2.y; so[6] = f3.x; so[7] = f3.y;
        }
    }
    __syncthreads();

    // out[b, c, n0+qq]: 32 consecutive n per store -> 128 B coalesced
    float* ob = out + (size_t)b * 128 * NPTS + n0;
    const int qq = tid & 31;
    const int c0 = tid >> 5;
#pragma unroll
    for (int pass = 0; pass < 4; pass++) {
        const int c = pass * 32 + c0;
        ob[(size_t)c * NPTS + qq] = sout[qq * 133 + c];
    }
}

extern "C" void kernel_launch(void* const* d_in, const int* in_sizes, int n_in,
                              void* d_out, int out_size)
{
    const float* x  = (const float*)d_in[0];   // (8, 2048, 3)
    const float* W1 = (const float*)d_in[1];   // (64, 3)
    const float* b1 = (const float*)d_in[2];   // (64,)
    const float* W2 = (const float*)d_in[3];   // (128, 64)
    const float* b2 = (const float*)d_in[4];   // (128,)
    float* out = (float*)d_out;                // (8, 128, 2048)

    feat_kernel<<<128, 512>>>(x, W1, b1, W2, b2);
    group_kernel<<<dim3(64, 8), 1024>>>(x, out);
}